// round 2
// baseline (speedup 1.0000x reference)
#include <cuda_runtime.h>

#define HW   262144      // 512*512
#define NB   8
#define NC   64
#define TPB  256

__global__ __launch_bounds__(TPB) void color_reduce_kernel(
    const float* __restrict__ x,
    const float* __restrict__ pal,
    float* __restrict__ out)
{
    // Palette duplicated pairwise so f32x2 broadcast operands load directly
    // as 64-bit register pairs from shared memory.
    __shared__ float4 spA[NC];   // {-2r, -2r, -2g, -2g}
    __shared__ float4 spB[NC];   // {-2b, -2b, cc,  cc }   cc = ||c||^2
    __shared__ float4 sc [NC];   // raw color

    int t = threadIdx.x;
    if (t < NC) {
        float r = pal[3 * t + 0];
        float g = pal[3 * t + 1];
        float b = pal[3 * t + 2];
        float cc = fmaf(r, r, fmaf(g, g, b * b));
        spA[t] = make_float4(-2.0f * r, -2.0f * r, -2.0f * g, -2.0f * g);
        spB[t] = make_float4(-2.0f * b, -2.0f * b, cc, cc);
        sc[t]  = make_float4(r, g, b, 0.0f);
    }
    __syncthreads();

    int gid = blockIdx.x * TPB + t;          // one thread = 4 consecutive pixels
    int b   = gid >> 16;                     // gid / (HW/4)
    int i   = (gid & 65535) * 4;
    size_t base = (size_t)b * (3 * HW) + i;

    float4 px = *(const float4*)(x + base);
    float4 py = *(const float4*)(x + base + HW);
    float4 pz = *(const float4*)(x + base + 2 * HW);

    // Pack pixel pairs into 64-bit f32x2 containers (register-pair aliasing).
    unsigned long long px01, px23, py01, py23, pz01, pz23;
    asm("mov.b64 %0, {%1,%2};" : "=l"(px01) : "f"(px.x), "f"(px.y));
    asm("mov.b64 %0, {%1,%2};" : "=l"(px23) : "f"(px.z), "f"(px.w));
    asm("mov.b64 %0, {%1,%2};" : "=l"(py01) : "f"(py.x), "f"(py.y));
    asm("mov.b64 %0, {%1,%2};" : "=l"(py23) : "f"(py.z), "f"(py.w));
    asm("mov.b64 %0, {%1,%2};" : "=l"(pz01) : "f"(pz.x), "f"(pz.y));
    asm("mov.b64 %0, {%1,%2};" : "=l"(pz23) : "f"(pz.z), "f"(pz.w));

    float bd0 = 3.4e38f, bd1 = 3.4e38f, bd2 = 3.4e38f, bd3 = 3.4e38f;
    float bf0 = 0.0f,    bf1 = 0.0f,    bf2 = 0.0f,    bf3 = 0.0f;

    #pragma unroll 16
    for (int k = 0; k < NC; ++k) {
        // A.x = {cx,cx}, A.y = {cy,cy}; B.x = {cz,cz}, B.y = {cc,cc}
        ulonglong2 A = *(ulonglong2*)&spA[k];
        ulonglong2 B = *(ulonglong2*)&spB[k];

        // Same rounding order as scalar version:
        // d = fma(px,cx, fma(py,cy, fma(pz,cz, cc)))  -- per-lane IEEE rn.
        unsigned long long d01, d23;
        asm("fma.rn.f32x2 %0, %1, %2, %3;" : "=l"(d01) : "l"(pz01), "l"(B.x), "l"(B.y));
        asm("fma.rn.f32x2 %0, %1, %2, %0;" : "+l"(d01) : "l"(py01), "l"(A.y));
        asm("fma.rn.f32x2 %0, %1, %2, %0;" : "+l"(d01) : "l"(px01), "l"(A.x));
        asm("fma.rn.f32x2 %0, %1, %2, %3;" : "=l"(d23) : "l"(pz23), "l"(B.x), "l"(B.y));
        asm("fma.rn.f32x2 %0, %1, %2, %0;" : "+l"(d23) : "l"(py23), "l"(A.y));
        asm("fma.rn.f32x2 %0, %1, %2, %0;" : "+l"(d23) : "l"(px23), "l"(A.x));

        float d0, d1, d2, d3;
        asm("mov.b64 {%0,%1}, %2;" : "=f"(d0), "=f"(d1) : "l"(d01));
        asm("mov.b64 {%0,%1}, %2;" : "=f"(d2), "=f"(d3) : "l"(d23));

        // Strict < keeps first minimum (matches argmin). Index carried as
        // float (FSEL, pred-as-data) so the whole triplet is FP-pipe eligible.
        float kf = (float)k;
        bf0 = (d0 < bd0) ? kf : bf0;  bd0 = fminf(bd0, d0);
        bf1 = (d1 < bd1) ? kf : bf1;  bd1 = fminf(bd1, d1);
        bf2 = (d2 < bd2) ? kf : bf2;  bd2 = fminf(bd2, d2);
        bf3 = (d3 < bd3) ? kf : bf3;  bd3 = fminf(bd3, d3);
    }

    int bi0 = (int)bf0;
    int bi1 = (int)bf1;
    int bi2 = (int)bf2;
    int bi3 = (int)bf3;

    float4 c0 = sc[bi0];
    float4 c1 = sc[bi1];
    float4 c2 = sc[bi2];
    float4 c3 = sc[bi3];

    *(float4*)(out + base)          = make_float4(c0.x, c1.x, c2.x, c3.x);
    *(float4*)(out + base + HW)     = make_float4(c0.y, c1.y, c2.y, c3.y);
    *(float4*)(out + base + 2 * HW) = make_float4(c0.z, c1.z, c2.z, c3.z);
}

extern "C" void kernel_launch(void* const* d_in, const int* in_sizes, int n_in,
                              void* d_out, int out_size)
{
    const float* x   = (const float*)d_in[0];
    const float* pal = (const float*)d_in[1];
    float*       out = (float*)d_out;

    int total_threads = NB * HW / 4;         // 524288
    color_reduce_kernel<<<total_threads / TPB, TPB>>>(x, pal, out);
}

// round 4
// speedup vs baseline: 1.0987x; 1.0987x over previous
#include <cuda_runtime.h>

#define HW   262144            // 512*512
#define NB   8
#define NC   64
#define G    16
#define NCELLS (G*G*G)         // 4096
#define EPS  1e-4f
#define TPB  256
#define GRID 456               // persistent: ~3 CTAs/SM * 152 SMs

// Cell record (16B): byte0 = count (or 64 = fallback), bytes 1..15 = candidate ids (ascending k)
__device__ uint4 g_cells[NCELLS];

// ---------------- LUT build: exact candidate superset per cell ----------------
__global__ void build_lut(const float* __restrict__ pal)
{
    int cell = blockIdx.x * blockDim.x + threadIdx.x;
    if (cell >= NCELLS) return;
    int cx = (cell >> 8) & 15, cy = (cell >> 4) & 15, cz = cell & 15;
    const float inv = 1.0f / G;
    float lox = cx * inv, hix = lox + inv;
    float loy = cy * inv, hiy = loy + inv;
    float loz = cz * inv, hiz = loz + inv;

    // threshold = min over colors of (max squared distance from anywhere in the box)
    float thr = 3.4e38f;
    for (int k = 0; k < NC; ++k) {
        float r = pal[3*k], g = pal[3*k+1], b = pal[3*k+2];
        float dx = fmaxf(r - lox, hix - r);     // farthest-endpoint distance per axis
        float dy = fmaxf(g - loy, hiy - g);
        float dz = fmaxf(b - loz, hiz - b);
        thr = fminf(thr, fmaf(dx,dx, fmaf(dy,dy, dz*dz)));
    }
    thr += EPS;   // margin >> fp ordering noise (~1e-6): keeps every possible fp winner

    unsigned int w0 = 0, w1 = 0, w2 = 0, w3 = 0;
    int cnt = 0;
    for (int k = 0; k < NC; ++k) {             // ascending k -> tie-break order preserved
        float r = pal[3*k], g = pal[3*k+1], b = pal[3*k+2];
        float dx = fmaxf(fmaxf(lox - r, r - hix), 0.0f);   // nearest-point distance per axis
        float dy = fmaxf(fmaxf(loy - g, g - hiy), 0.0f);
        float dz = fmaxf(fmaxf(loz - b, b - hiz), 0.0f);
        float dmin = fmaf(dx,dx, fmaf(dy,dy, dz*dz));
        if (dmin <= thr) {
            if      (cnt < 3)  w0 |= (unsigned)k << (8*(cnt+1));
            else if (cnt < 7)  w1 |= (unsigned)k << (8*(cnt-3));
            else if (cnt < 11) w2 |= (unsigned)k << (8*(cnt-7));
            else if (cnt < 15) w3 |= (unsigned)k << (8*(cnt-11));
            cnt++;
        }
    }
    unsigned int c = (cnt > 15) ? 64u : (unsigned)cnt;     // 64 = full-scan fallback
    g_cells[cell] = make_uint4(c | w0, w1, w2, w3);
}

// ---------------- main kernel: persistent, LUT + palette in shared ----------------
extern __shared__ uint4 s_raw[];

__device__ __forceinline__ void quantize_px(
    float r, float g, float b,
    const uint4* __restrict__ cells,
    const float4* __restrict__ sp,
    float& bd, int& bi)
{
    // exact cell: *16 is a power-of-2 scale -> no rounding, no boundary misassignment
    int ci = (((int)(r * 16.0f)) << 8) | (((int)(g * 16.0f)) << 4) | ((int)(b * 16.0f));
    uint4 rec = cells[ci];
    unsigned int cnt = rec.x & 0xffu;
    bd = 3.4e38f; bi = 0;

    if (cnt <= 15u) {
        unsigned long long wa = ((unsigned long long)rec.y << 24) | (rec.x >> 8);  // cands 0..6
        unsigned long long wb = ((unsigned long long)rec.w << 32) | rec.z;          // cands 7..14
        unsigned int n0 = cnt < 7u ? cnt : 7u;
        for (unsigned int j = 0; j < n0; ++j) {
            int k = (int)(wa & 0xff); wa >>= 8;
            float4 c = sp[k];
            float d = fmaf(r, c.x, fmaf(g, c.y, fmaf(b, c.z, c.w)));  // identical to R1
            if (d < bd) { bd = d; bi = k; }
        }
        for (unsigned int j = 7; j < cnt; ++j) {
            int k = (int)(wb & 0xff); wb >>= 8;
            float4 c = sp[k];
            float d = fmaf(r, c.x, fmaf(g, c.y, fmaf(b, c.z, c.w)));
            if (d < bd) { bd = d; bi = k; }
        }
    } else {  // rare fallback: full scan (identical semantics to round 1)
        for (int k = 0; k < NC; ++k) {
            float4 c = sp[k];
            float d = fmaf(r, c.x, fmaf(g, c.y, fmaf(b, c.z, c.w)));
            if (d < bd) { bd = d; bi = k; }
        }
    }
}

__global__ __launch_bounds__(TPB) void color_reduce_kernel(
    const float* __restrict__ x,
    const float* __restrict__ pal,
    float* __restrict__ out)
{
    uint4*  cells = s_raw;                         // 4096 * 16B = 64KB
    float4* sp    = (float4*)(s_raw + NCELLS);     // {-2r,-2g,-2b,||c||^2} : 1KB
    float4* sc    = sp + NC;                       // raw colors            : 1KB

    int t = threadIdx.x;
    for (int i = t; i < NCELLS; i += TPB) cells[i] = g_cells[i];
    if (t < NC) {
        float r = pal[3*t], g = pal[3*t+1], b = pal[3*t+2];
        sp[t] = make_float4(-2.0f*r, -2.0f*g, -2.0f*b, fmaf(r,r, fmaf(g,g, b*b)));
        sc[t] = make_float4(r, g, b, 0.0f);
    }
    __syncthreads();

    const int nquads = NB * HW / 4;                // 524288
    for (int q = blockIdx.x * TPB + t; q < nquads; q += GRID * TPB) {
        int bIdx = q >> 16;                        // quad index within batch: HW/4 = 65536
        int i    = (q & 65535) * 4;
        size_t base = (size_t)bIdx * (3 * HW) + i;

        float4 px = *(const float4*)(x + base);
        float4 py = *(const float4*)(x + base + HW);
        float4 pz = *(const float4*)(x + base + 2 * HW);

        float bd; int b0, b1, b2, b3;
        quantize_px(px.x, py.x, pz.x, cells, sp, bd, b0);
        quantize_px(px.y, py.y, pz.y, cells, sp, bd, b1);
        quantize_px(px.z, py.z, pz.z, cells, sp, bd, b2);
        quantize_px(px.w, py.w, pz.w, cells, sp, bd, b3);

        float4 c0 = sc[b0], c1 = sc[b1], c2 = sc[b2], c3 = sc[b3];
        *(float4*)(out + base)          = make_float4(c0.x, c1.x, c2.x, c3.x);
        *(float4*)(out + base + HW)     = make_float4(c0.y, c1.y, c2.y, c3.y);
        *(float4*)(out + base + 2 * HW) = make_float4(c0.z, c1.z, c2.z, c3.z);
    }
}

extern "C" void kernel_launch(void* const* d_in, const int* in_sizes, int n_in,
                              void* d_out, int out_size)
{
    const float* x   = (const float*)d_in[0];
    const float* pal = (const float*)d_in[1];
    float*       out = (float*)d_out;

    const int smem_bytes = NCELLS * 16 + 2 * NC * 16;   // 67584
    static int configured = 0;
    if (!configured) {
        cudaFuncSetAttribute(color_reduce_kernel,
                             cudaFuncAttributeMaxDynamicSharedMemorySize, smem_bytes);
        configured = 1;
    }

    build_lut<<<NCELLS / 64, 64>>>(pal);
    color_reduce_kernel<<<GRID, TPB, smem_bytes>>>(x, pal, out);
}